// round 17
// baseline (speedup 1.0000x reference)
#include <cuda_runtime.h>
#include <math.h>

// ChamferLoss: B=8, N=M=4096, D=3 — dual-order sort (Morton src / row-major tgt, 64x64 grid)
// + smem-staged warp-uniform pruned NN with warp-chunk load balancing.

#define BATCH    8
#define NPTS     4096
#define NCLOUD   16
#define GRID     64
#define NCELL    (GRID * GRID)          // 4096
#define XMIN     (-3.2f)
#define CELLW    0.1f
#define INV_CELLW 10.0f
#define THREADS  256
#define SLICES   16
#define NCOMBO   16
#define NBLOCKS  (NCOMBO * SLICES)      // 256
#define NWARPS   (THREADS / 32)

__device__ float4 g_src[NCLOUD][NPTS];           // Morton-cell-sorted (x,y,z,|p|^2)
__device__ float4 g_tgt[NCLOUD][NPTS];           // row-major-cell-sorted
__device__ int    g_rowstart[NCLOUD][NCELL + 1];
__device__ double g_sum  = 0.0;
__device__ unsigned int g_tick = 0;

static __device__ __forceinline__ int clampg(int v) { return min(max(v, 0), GRID - 1); }
static __device__ __forceinline__ unsigned int part1by1(unsigned int x) {
    x &= 0x0000FFFFu;
    x = (x | (x << 8)) & 0x00FF00FFu;
    x = (x | (x << 4)) & 0x0F0F0F0Fu;
    x = (x | (x << 2)) & 0x33333333u;
    x = (x | (x << 1)) & 0x55555555u;
    return x;
}
static __device__ __forceinline__ int morton(int cx, int cy) {
    return (int)(part1by1((unsigned)cx) | (part1by1((unsigned)cy) << 1));
}

// ---------------- Kernel 1: two-pass counting sort per cloud ----------------
__global__ __launch_bounds__(512) void sort_kernel(
    const float* __restrict__ pred,
    const float* __restrict__ targ)
{
    __shared__ int cnt[NCELL];     // 16 KB
    __shared__ int ofs[NCELL];     // 16 KB
    __shared__ int wtot[16];

    const int c = blockIdx.x;
    const int b = c >> 1;
    const float* __restrict__ src = ((c & 1) ? targ : pred) + (size_t)b * NPTS * 3;
    const int tid = threadIdx.x;

    for (int pass = 0; pass < 2; pass++) {      // 0: row-major -> g_tgt; 1: Morton -> g_src
        for (int k = tid; k < NCELL; k += 512) cnt[k] = 0;
        __syncthreads();
        #pragma unroll
        for (int i = tid; i < NPTS; i += 512) {
            int cx = clampg((int)((src[3 * i] - XMIN) * INV_CELLW));
            int cy = clampg((int)((src[3 * i + 1] - XMIN) * INV_CELLW));
            int idx = pass ? morton(cx, cy) : ((cy << 6) | cx);
            atomicAdd(&cnt[idx], 1);
        }
        __syncthreads();

        {   // exclusive prefix over 4096 cells: 8 per thread
            const int base = tid * 8;
            int v0 = cnt[base],     v1 = cnt[base + 1], v2 = cnt[base + 2], v3 = cnt[base + 3];
            int v4 = cnt[base + 4], v5 = cnt[base + 5], v6 = cnt[base + 6], v7 = cnt[base + 7];
            int tot = v0 + v1 + v2 + v3 + v4 + v5 + v6 + v7;
            int inc = tot;
            #pragma unroll
            for (int o = 1; o < 32; o <<= 1) {
                int n = __shfl_up_sync(0xFFFFFFFFu, inc, o);
                if ((tid & 31) >= o) inc += n;
            }
            if ((tid & 31) == 31) wtot[tid >> 5] = inc;
            __syncthreads();
            if (tid == 0) {
                int r = 0;
                #pragma unroll
                for (int w = 0; w < 16; w++) { int t = wtot[w]; wtot[w] = r; r += t; }
            }
            __syncthreads();
            int run = (inc - tot) + wtot[tid >> 5];
            int vs[8] = {v0, v1, v2, v3, v4, v5, v6, v7};
            #pragma unroll
            for (int j = 0; j < 8; j++) {
                ofs[base + j] = run;
                if (!pass) g_rowstart[c][base + j] = run;
                run += vs[j];
            }
            if (!pass && tid == 511) g_rowstart[c][NCELL] = run;
        }
        __syncthreads();

        #pragma unroll
        for (int i = tid; i < NPTS; i += 512) {
            float x = src[3 * i], y = src[3 * i + 1], z = src[3 * i + 2];
            float w = fmaf(x, x, fmaf(y, y, z * z));
            int cx = clampg((int)((x - XMIN) * INV_CELLW));
            int cy = clampg((int)((y - XMIN) * INV_CELLW));
            int idx = pass ? morton(cx, cy) : ((cy << 6) | cx);
            int pos = atomicAdd(&ofs[idx], 1);
            if (pass) g_src[c][pos] = make_float4(x, y, z, w);
            else      g_tgt[c][pos] = make_float4(x, y, z, w);
        }
        __syncthreads();
    }
}

// ---------------- Kernel 2: staged row-major cloud + Morton sources ----------------
struct Smem {
    float4 tgt[NPTS];            // 64 KB
    int    cst[NCELL + 1];       // 16.4 KB
    float  warpsums[NWARPS];
    unsigned int s_done;
};

__global__ __launch_bounds__(THREADS) void search_kernel(float* __restrict__ out)
{
    extern __shared__ char smem_raw[];
    Smem* s = (Smem*)smem_raw;
    const int tid  = threadIdx.x;
    const int lane = tid & 31;
    const int wid  = tid >> 5;

    const int combo = blockIdx.x / SLICES;
    const int slice = blockIdx.x % SLICES;
    const int b     = combo >> 1;
    const int dir   = combo & 1;
    const int cs    = b * 2 + dir;
    const int ct    = b * 2 + (dir ^ 1);

    // Stage row-major target cloud + prefix (coalesced)
    {
        const float4* __restrict__ g = g_tgt[ct];
        #pragma unroll
        for (int k = 0; k < NPTS / THREADS; k++)
            s->tgt[k * THREADS + tid] = g[k * THREADS + tid];
        for (int k = tid; k < NCELL + 1; k += THREADS)
            s->cst[k] = g_rowstart[ct][k];
    }

    // Warp-chunk shuffle: spread Morton chunks across blocks for load balance.
    // chunk in [0,128); lanes stay 32 consecutive Morton points (compact quad).
    const int chunk = wid * SLICES + slice;
    const float4 p = g_src[cs][chunk * 32 + lane];
    const float mx = -2.0f * p.x, my = -2.0f * p.y, mz = -2.0f * p.z;

    __syncthreads();

    float bA = INFINITY, bB = INFINITY, bC = INFINITY, bD = INFINITY;

    // One contiguous segment per grid row (row-major target order)
    auto scan_rows = [&](int ax0, int ax1, int ay0, int ay1) {
        for (int ry = ay0; ry <= ay1; ry++) {
            const int j1 = s->cst[(ry << 6) + ax1 + 1];
            int j = s->cst[(ry << 6) + ax0];
            for (; j + 3 < j1; j += 4) {          // broadcast LDS, 4-way MLP
                float4 t0 = s->tgt[j];
                float4 t1 = s->tgt[j + 1];
                float4 t2 = s->tgt[j + 2];
                float4 t3 = s->tgt[j + 3];
                bA = fminf(bA, fmaf(mx, t0.x, fmaf(my, t0.y, fmaf(mz, t0.z, t0.w))));
                bB = fminf(bB, fmaf(mx, t1.x, fmaf(my, t1.y, fmaf(mz, t1.z, t1.w))));
                bC = fminf(bC, fmaf(mx, t2.x, fmaf(my, t2.y, fmaf(mz, t2.z, t2.w))));
                bD = fminf(bD, fmaf(mx, t3.x, fmaf(my, t3.y, fmaf(mz, t3.z, t3.w))));
            }
            for (; j < j1; j++) {
                float4 t0 = s->tgt[j];
                bA = fminf(bA, fmaf(mx, t0.x, fmaf(my, t0.y, fmaf(mz, t0.z, t0.w))));
            }
        }
    };

    // Warp bbox in cell space
    int pcx = clampg((int)((p.x - XMIN) * INV_CELLW));
    int pcy = clampg((int)((p.y - XMIN) * INV_CELLW));
    int bx0 = pcx, bx1 = pcx, by0 = pcy, by1 = pcy;
    #pragma unroll
    for (int o = 16; o > 0; o >>= 1) {
        bx0 = min(bx0, __shfl_xor_sync(0xFFFFFFFFu, bx0, o));
        bx1 = max(bx1, __shfl_xor_sync(0xFFFFFFFFu, bx1, o));
        by0 = min(by0, __shfl_xor_sync(0xFFFFFFFFu, by0, o));
        by1 = max(by1, __shfl_xor_sync(0xFFFFFFFFu, by1, o));
    }

    // Phase A: bbox + 1 ring; expand perimeter while empty (warp-uniform)
    int wx0 = max(bx0 - 1, 0), wx1 = min(bx1 + 1, GRID - 1);
    int wy0 = max(by0 - 1, 0), wy1 = min(by1 + 1, GRID - 1);
    scan_rows(wx0, wx1, wy0, wy1);
    while (fminf(fminf(bA, bB), fminf(bC, bD)) == INFINITY &&
           !(wx0 == 0 && wx1 == GRID - 1 && wy0 == 0 && wy1 == GRID - 1)) {
        int nx0 = max(wx0 - 1, 0), nx1 = min(wx1 + 1, GRID - 1);
        int ny0 = max(wy0 - 1, 0), ny1 = min(wy1 + 1, GRID - 1);
        if (ny0 < wy0) scan_rows(nx0, nx1, ny0, ny0);
        if (ny1 > wy1) scan_rows(nx0, nx1, ny1, ny1);
        if (nx0 < wx0) scan_rows(nx0, nx0, wy0, wy1);
        if (nx1 > wx1) scan_rows(nx1, nx1, wy0, wy1);
        wx0 = nx0; wx1 = nx1; wy0 = ny0; wy1 = ny1;
    }
    float best = fminf(fminf(bA, bB), fminf(bC, bD));
    float d = sqrtf(fmaxf(best + p.w, 0.0f));

    // Phase B: per-lane margin; ballot-gated warp-union delta rescan
    float mgl = (wx0 == 0)        ? 1e30f : p.x - (XMIN + wx0 * CELLW);
    float mgr = (wx1 == GRID - 1) ? 1e30f : (XMIN + (wx1 + 1) * CELLW) - p.x;
    float mgb = (wy0 == 0)        ? 1e30f : p.y - (XMIN + wy0 * CELLW);
    float mgt = (wy1 == GRID - 1) ? 1e30f : (XMIN + (wy1 + 1) * CELLW) - p.y;
    float margin = fminf(fminf(mgl, mgr), fminf(mgb, mgt));
    const bool needy = (d >= margin * 0.9999f);

    if (__ballot_sync(0xFFFFFFFFu, needy)) {
        float dc = d * 1.0001f + 1e-6f;
        int fx0 = needy ? clampg((int)floorf((p.x - dc - XMIN) * INV_CELLW)) : GRID;
        int fx1 = needy ? clampg((int)floorf((p.x + dc - XMIN) * INV_CELLW)) : -1;
        int fy0 = needy ? clampg((int)floorf((p.y - dc - XMIN) * INV_CELLW)) : GRID;
        int fy1 = needy ? clampg((int)floorf((p.y + dc - XMIN) * INV_CELLW)) : -1;
        #pragma unroll
        for (int o = 16; o > 0; o >>= 1) {
            fx0 = min(fx0, __shfl_xor_sync(0xFFFFFFFFu, fx0, o));
            fx1 = max(fx1, __shfl_xor_sync(0xFFFFFFFFu, fx1, o));
            fy0 = min(fy0, __shfl_xor_sync(0xFFFFFFFFu, fy0, o));
            fy1 = max(fy1, __shfl_xor_sync(0xFFFFFFFFu, fy1, o));
        }
        fx0 = min(fx0, wx0); fx1 = max(fx1, wx1);
        fy0 = min(fy0, wy0); fy1 = max(fy1, wy1);
        for (int ry = fy0; ry <= fy1; ry++) {
            if (ry < wy0 || ry > wy1) {
                scan_rows(fx0, fx1, ry, ry);
            } else {
                if (fx0 < wx0) scan_rows(fx0, wx0 - 1, ry, ry);
                if (fx1 > wx1) scan_rows(wx1 + 1, fx1, ry, ry);
            }
        }
        best = fminf(fminf(bA, bB), fminf(bC, bD));
        d = sqrtf(fmaxf(best + p.w, 0.0f));
    }

    // Reduction
    float acc = d;
    #pragma unroll
    for (int o = 16; o > 0; o >>= 1)
        acc += __shfl_xor_sync(0xFFFFFFFFu, acc, o);
    if (lane == 0) s->warpsums[wid] = acc;
    __syncthreads();
    if (tid == 0) {
        float v = 0.0f;
        #pragma unroll
        for (int k = 0; k < NWARPS; k++) v += s->warpsums[k];
        atomicAdd(&g_sum, (double)v / ((double)BATCH * (double)NPTS));
    }

    // Ticket: last block publishes + resets
    __threadfence();
    if (tid == 0) s->s_done = atomicAdd(&g_tick, 1u);
    __syncthreads();
    if (s->s_done == NBLOCKS - 1 && tid == 0) {
        double total = atomicAdd(&g_sum, 0.0);   // atomic read
        out[0] = (float)total;
        g_sum  = 0.0;
        g_tick = 0;
    }
}

extern "C" void kernel_launch(void* const* d_in, const int* in_sizes, int n_in,
                              void* d_out, int out_size) {
    const float* pred = (const float*)d_in[0];
    const float* targ = (const float*)d_in[1];
    float* out = (float*)d_out;

    static bool attr_set = false;
    if (!attr_set) {
        cudaFuncSetAttribute(search_kernel,
                             cudaFuncAttributeMaxDynamicSharedMemorySize,
                             (int)sizeof(Smem));
        attr_set = true;
    }
    sort_kernel<<<NCLOUD, 512>>>(pred, targ);
    search_kernel<<<NBLOCKS, THREADS, sizeof(Smem)>>>(out);
}